// round 2
// baseline (speedup 1.0000x reference)
#include <cuda_runtime.h>
#include <math.h>

// ---------------- static scratch (no allocations allowed) ----------------
__device__ float g_bufA[16777216];   // 64 MB ping
__device__ float g_bufB[16777216];   // 64 MB pong
__device__ float g_m1[1048576];      // 4*64^3
__device__ float g_m2[131072];       // 4*32^3
__device__ float g_m3[16384];        // 4*16^3
__device__ int   g_cnt[3];
__device__ float g_part[128 * 1024]; // per-block BN partials (sum | sumsq)
__device__ float g_scale[512];
__device__ float g_shift[512];
__device__ float g_ppart[4 * 16 * 512];
__device__ float g_cpart[4 * 16];
__device__ float g_pooled[4 * 512];

#define EPSBN 1e-5f

// ---------------- mask pooling (2x2x2 max) + active count ----------------
template <typename T>
__global__ void pool_mask_kernel(const T* __restrict__ min_, float* __restrict__ mout,
                                 int* __restrict__ cnt, int B, int Dout) {
    int Din = Dout * 2;
    int M = B * Dout * Dout * Dout;
    int site = blockIdx.x * blockDim.x + threadIdx.x;
    int active = 0;
    if (site < M) {
        int ow = site % Dout; int t = site / Dout;
        int oh = t % Dout; t /= Dout;
        int od = t % Dout; int b = t / Dout;
        int iz0 = od * 2, iy0 = oh * 2, ix0 = ow * 2;
        bool a = false;
        #pragma unroll
        for (int dz = 0; dz < 2; dz++)
            #pragma unroll
            for (int dy = 0; dy < 2; dy++)
                #pragma unroll
                for (int dx = 0; dx < 2; dx++) {
                    T v = min_[(((long)(b * Din + iz0 + dz) * Din + iy0 + dy) * Din) + ix0 + dx];
                    a = a || (v != (T)0);
                }
        mout[site] = a ? 1.f : 0.f;
        active = a ? 1 : 0;
    }
    unsigned bal = __ballot_sync(0xffffffffu, active);
    __shared__ int ws[8];
    if ((threadIdx.x & 31) == 0) ws[threadIdx.x >> 5] = __popc(bal);
    __syncthreads();
    if (threadIdx.x == 0) {
        int t = 0;
        for (int i = 0; i < (int)(blockDim.x >> 5); i++) t += ws[i];
        atomicAdd(cnt, t);
    }
}

// ---------------- conv1a: 128^3 x1 -> 64^3 x16, stride 2 ----------------
__global__ void __launch_bounds__(256) conv1a_kernel(
    const float* __restrict__ x, const int* __restrict__ mask,
    const float* __restrict__ w, const float* __restrict__ m1, float* __restrict__ y) {
    __shared__ float wsh[432];
    for (int i = threadIdx.x; i < 432; i += 256) wsh[i] = w[i];
    __syncthreads();
    int site = blockIdx.x * 256 + threadIdx.x;   // 4*64^3 = 1048576, divisible by 256
    int ow = site & 63; int t = site >> 6;
    int oh = t & 63; t >>= 6;
    int od = t & 63; int b = t >> 6;
    float acc[16];
    #pragma unroll
    for (int c = 0; c < 16; c++) acc[c] = 0.f;
    #pragma unroll
    for (int tz = 0; tz < 3; tz++) {
        int iz = od * 2 - 1 + tz;
        if ((unsigned)iz >= 128u) continue;
        #pragma unroll
        for (int ty = 0; ty < 3; ty++) {
            int iy = oh * 2 - 1 + ty;
            if ((unsigned)iy >= 128u) continue;
            #pragma unroll
            for (int tx = 0; tx < 3; tx++) {
                int ix = ow * 2 - 1 + tx;
                if ((unsigned)ix >= 128u) continue;
                int idx = ((b * 128 + iz) * 128 + iy) * 128 + ix;
                if (mask[idx]) {
                    float v = x[idx];
                    int tap = (tz * 3 + ty) * 3 + tx;
                    #pragma unroll
                    for (int c = 0; c < 16; c++) acc[c] += v * wsh[tap * 16 + c];
                }
            }
        }
    }
    float mk = m1[site];
    float* o = y + (long)site * 16;
    #pragma unroll
    for (int q = 0; q < 4; q++) {
        float4 v = make_float4(acc[q*4]*mk, acc[q*4+1]*mk, acc[q*4+2]*mk, acc[q*4+3]*mk);
        *(float4*)(o + q * 4) = v;
    }
}

// ---------------- conv1b: 64^3 16->16, stride 1, 2 sites/thread ----------------
__global__ void __launch_bounds__(256) conv1b_kernel(
    const float* __restrict__ in, const float* __restrict__ w,
    const float* __restrict__ m, float* __restrict__ out) {
    __shared__ float wsh[6912];
    for (int i = threadIdx.x; i < 6912; i += 256) wsh[i] = w[i];
    __syncthreads();
    int pair = blockIdx.x * 256 + threadIdx.x;  // 524288 pairs
    int s0 = pair * 2;
    int ow = s0 & 63; int t = s0 >> 6;
    int oh = t & 63; t >>= 6;
    int od = t & 63; int b = t >> 6;
    float acc0[16], acc1[16];
    #pragma unroll
    for (int c = 0; c < 16; c++) { acc0[c] = 0.f; acc1[c] = 0.f; }
    #pragma unroll
    for (int tz = 0; tz < 3; tz++) {
        int iz = od - 1 + tz;
        if ((unsigned)iz >= 64u) continue;
        #pragma unroll
        for (int ty = 0; ty < 3; ty++) {
            int iy = oh - 1 + ty;
            if ((unsigned)iy >= 64u) continue;
            int rowbase = ((b * 64 + iz) * 64 + iy) * 64;
            #pragma unroll
            for (int tx = 0; tx < 3; tx++) {
                int ix0 = ow - 1 + tx;
                int ix1 = ix0 + 1;
                int tap = (tz * 3 + ty) * 3 + tx;
                const float* wp = wsh + tap * 256;
                bool ok0 = (unsigned)ix0 < 64u;
                bool ok1 = (unsigned)ix1 < 64u;
                float4 v0q[4], v1q[4];
                #pragma unroll
                for (int q = 0; q < 4; q++) {
                    v0q[q] = ok0 ? *(const float4*)(in + (long)(rowbase + ix0) * 16 + q * 4)
                                 : make_float4(0, 0, 0, 0);
                    v1q[q] = ok1 ? *(const float4*)(in + (long)(rowbase + ix1) * 16 + q * 4)
                                 : make_float4(0, 0, 0, 0);
                }
                const float* v0 = (const float*)v0q;
                const float* v1 = (const float*)v1q;
                #pragma unroll
                for (int ci = 0; ci < 16; ci++) {
                    float a0 = v0[ci], a1 = v1[ci];
                    #pragma unroll
                    for (int q = 0; q < 4; q++) {
                        float4 wv = *(const float4*)(wp + ci * 16 + q * 4);
                        acc0[q*4+0] += a0 * wv.x; acc0[q*4+1] += a0 * wv.y;
                        acc0[q*4+2] += a0 * wv.z; acc0[q*4+3] += a0 * wv.w;
                        acc1[q*4+0] += a1 * wv.x; acc1[q*4+1] += a1 * wv.y;
                        acc1[q*4+2] += a1 * wv.z; acc1[q*4+3] += a1 * wv.w;
                    }
                }
            }
        }
    }
    float mk0 = m[s0], mk1 = m[s0 + 1];
    #pragma unroll
    for (int q = 0; q < 4; q++) {
        *(float4*)(out + (long)s0 * 16 + q * 4) =
            make_float4(acc0[q*4]*mk0, acc0[q*4+1]*mk0, acc0[q*4+2]*mk0, acc0[q*4+3]*mk0);
        *(float4*)(out + (long)(s0 + 1) * 16 + q * 4) =
            make_float4(acc1[q*4]*mk1, acc1[q*4+1]*mk1, acc1[q*4+2]*mk1, acc1[q*4+3]*mk1);
    }
}

// ---------------- implicit GEMM conv: BM=64, BN=64, BK=16, 4x4/thread ----------------
template <int CIN, int COUT, int S>
__global__ void __launch_bounds__(256) conv_igemm(
    const float* __restrict__ in, const float* __restrict__ w,
    const float* __restrict__ mout, float* __restrict__ out,
    int B, int Din, int Dout) {
    constexpr int BK = 16;
    constexpr int K = 27 * CIN;
    __shared__ float As[BK][64];
    __shared__ float Bs[BK][64];
    __shared__ int sB[64], sZ[64], sY[64], sX[64];

    const int tid = threadIdx.x;
    const int m0 = blockIdx.x * 64;
    const int n0 = blockIdx.y * 64;

    if (tid < 64) {
        int mm = m0 + tid;
        int ow = mm % Dout; int t = mm / Dout;
        int oh = t % Dout; t /= Dout;
        int od = t % Dout; int b = t / Dout;
        sB[tid] = b; sZ[tid] = od * S - 1; sY[tid] = oh * S - 1; sX[tid] = ow * S - 1;
    }
    __syncthreads();

    const int am = tid >> 2;
    const int ak = (tid & 3) << 2;
    const int aB = sB[am], aZ = sZ[am], aY = sY[am], aX = sX[am];
    const int bk = tid >> 4;
    const int bn = (tid & 15) << 2;
    const int ty = tid >> 4;
    const int tx = tid & 15;

    float acc[4][4];
    #pragma unroll
    for (int i = 0; i < 4; i++)
        #pragma unroll
        for (int j = 0; j < 4; j++) acc[i][j] = 0.f;

    for (int k0 = 0; k0 < K; k0 += BK) {
        int kA = k0 + ak;
        int tap = kA / CIN;
        int ci = kA - tap * CIN;
        int tz = tap / 9; int tr = tap - tz * 9;
        int tyy = tr / 3; int txx = tr - tyy * 3;
        int iz = aZ + tz, iy = aY + tyy, ix = aX + txx;
        float4 va = make_float4(0, 0, 0, 0);
        if ((unsigned)iz < (unsigned)Din && (unsigned)iy < (unsigned)Din &&
            (unsigned)ix < (unsigned)Din) {
            int idx = (((aB * Din + iz) * Din + iy) * Din + ix) * CIN + ci;
            va = *(const float4*)(in + idx);
        }
        As[ak + 0][am] = va.x; As[ak + 1][am] = va.y;
        As[ak + 2][am] = va.z; As[ak + 3][am] = va.w;

        int kB = k0 + bk;
        *(float4*)&Bs[bk][bn] = *(const float4*)(w + (long)kB * COUT + n0 + bn);
        __syncthreads();

        #pragma unroll
        for (int kk = 0; kk < BK; kk++) {
            float4 a = *(const float4*)&As[kk][ty << 2];
            float4 b = *(const float4*)&Bs[kk][tx << 2];
            acc[0][0] += a.x * b.x; acc[0][1] += a.x * b.y; acc[0][2] += a.x * b.z; acc[0][3] += a.x * b.w;
            acc[1][0] += a.y * b.x; acc[1][1] += a.y * b.y; acc[1][2] += a.y * b.z; acc[1][3] += a.y * b.w;
            acc[2][0] += a.z * b.x; acc[2][1] += a.z * b.y; acc[2][2] += a.z * b.z; acc[2][3] += a.z * b.w;
            acc[3][0] += a.w * b.x; acc[3][1] += a.w * b.y; acc[3][2] += a.w * b.z; acc[3][3] += a.w * b.w;
        }
        __syncthreads();
    }

    #pragma unroll
    for (int i = 0; i < 4; i++) {
        int mm = m0 + (ty << 2) + i;
        float mk = mout[mm];
        float4 o = make_float4(acc[i][0] * mk, acc[i][1] * mk, acc[i][2] * mk, acc[i][3] * mk);
        *(float4*)(out + (long)mm * COUT + n0 + (tx << 2)) = o;
    }
}

// ---------------- BN: deterministic two-level reduction ----------------
template <int C>
__global__ void __launch_bounds__(256) bn_reduce(const float* __restrict__ y, int nsites,
                                                 float* __restrict__ part) {
    constexpr int GP = C / 4;       // threads per site
    constexpr int NG = 256 / GP;    // sites per block step
    int tid = threadIdx.x;
    int g = tid / GP;
    int lane = tid - g * GP;
    int c0 = lane * 4;
    float s0 = 0, s1 = 0, s2 = 0, s3 = 0;
    float q0 = 0, q1 = 0, q2 = 0, q3 = 0;
    for (int site = blockIdx.x * NG + g; site < nsites; site += gridDim.x * NG) {
        float4 v = *(const float4*)(y + (long)site * C + c0);
        s0 += v.x; s1 += v.y; s2 += v.z; s3 += v.w;
        q0 += v.x * v.x; q1 += v.y * v.y; q2 += v.z * v.z; q3 += v.w * v.w;
    }
    __shared__ float sm[NG][C];
    __shared__ float sq[NG][C];
    sm[g][c0 + 0] = s0; sm[g][c0 + 1] = s1; sm[g][c0 + 2] = s2; sm[g][c0 + 3] = s3;
    sq[g][c0 + 0] = q0; sq[g][c0 + 1] = q1; sq[g][c0 + 2] = q2; sq[g][c0 + 3] = q3;
    __syncthreads();
    for (int c = tid; c < C; c += 256) {
        float a = 0, b = 0;
        #pragma unroll 4
        for (int gg = 0; gg < NG; gg++) { a += sm[gg][c]; b += sq[gg][c]; }
        part[blockIdx.x * (2 * C) + c] = a;
        part[blockIdx.x * (2 * C) + C + c] = b;
    }
}

template <int C>
__global__ void bn_finalize(const float* __restrict__ part, const int* __restrict__ cntp,
                            const float* __restrict__ gamma, const float* __restrict__ beta,
                            float* __restrict__ scale, float* __restrict__ shift) {
    int c = threadIdx.x;
    if (c >= C) return;
    float s = 0, q = 0;
    for (int nb = 0; nb < 128; nb++) {
        s += part[nb * 2 * C + c];
        q += part[nb * 2 * C + C + c];
    }
    float cnt = (float)cntp[0];
    float mean = s / cnt;
    float var = q / cnt - mean * mean;
    float sc = gamma[c] * rsqrtf(var + EPSBN);
    scale[c] = sc;
    shift[c] = beta[c] - mean * sc;
}

template <int C>
__global__ void bn_apply(float* __restrict__ y, const float* __restrict__ m,
                         const float* __restrict__ scale, const float* __restrict__ shift,
                         int nsites) {
    __shared__ float sc[C], sh[C];
    for (int i = threadIdx.x; i < C; i += blockDim.x) { sc[i] = scale[i]; sh[i] = shift[i]; }
    __syncthreads();
    long total = (long)nsites * (C / 4);
    long i = (long)blockIdx.x * blockDim.x + threadIdx.x;
    if (i >= total) return;
    float4 v = ((float4*)y)[i];
    int cq = (int)(i % (C / 4)) * 4;
    float mk = m[i / (C / 4)];
    float a;
    a = v.x * sc[cq + 0] + sh[cq + 0]; v.x = (a > 0.f ? a : expm1f(a)) * mk;
    a = v.y * sc[cq + 1] + sh[cq + 1]; v.y = (a > 0.f ? a : expm1f(a)) * mk;
    a = v.z * sc[cq + 2] + sh[cq + 2]; v.z = (a > 0.f ? a : expm1f(a)) * mk;
    a = v.w * sc[cq + 3] + sh[cq + 3]; v.w = (a > 0.f ? a : expm1f(a)) * mk;
    ((float4*)y)[i] = v;
}

// ---------------- global pooling ----------------
__global__ void pool_partial(const float* __restrict__ y, const float* __restrict__ m3,
                             float* __restrict__ ppart, float* __restrict__ cpart) {
    int b = blockIdx.x;
    int g = blockIdx.y;
    int c = threadIdx.x; // 512
    float s = 0;
    int sbase = g * 256;
    for (int k = 0; k < 256; k++) s += y[((long)(b * 4096 + sbase + k)) * 512 + c];
    ppart[(b * 16 + g) * 512 + c] = s;
    __shared__ float red[512];
    red[c] = (c < 256) ? m3[b * 4096 + sbase + c] : 0.f;
    __syncthreads();
    for (int st = 256; st > 0; st >>= 1) {
        if (c < st) red[c] += red[c + st];
        __syncthreads();
    }
    if (c == 0) cpart[b * 16 + g] = red[0];
}

__global__ void pool_final(const float* __restrict__ ppart, const float* __restrict__ cpart,
                           float* __restrict__ pooled) {
    int b = blockIdx.x;
    int c = threadIdx.x;
    float s = 0, cnt = 0;
    for (int g = 0; g < 16; g++) {
        s += ppart[(b * 16 + g) * 512 + c];
        cnt += cpart[b * 16 + g];
    }
    pooled[b * 512 + c] = s / cnt;
}

// ---------------- heads: pooled @ wm + bm, pooled @ wv + bv ----------------
__global__ void heads_kernel(const float* __restrict__ pooled,
                             const float* __restrict__ wm, const float* __restrict__ bm,
                             const float* __restrict__ wv, const float* __restrict__ bv,
                             float* __restrict__ out) {
    int b = blockIdx.x;
    int j = threadIdx.x; // 512
    __shared__ float p[512];
    p[j] = pooled[b * 512 + j];
    __syncthreads();
    float sm_ = bm[j], sv = bv[j];
    for (int c = 0; c < 512; c++) {
        float pv = p[c];
        sm_ += pv * wm[c * 512 + j];
        sv += pv * wv[c * 512 + j];
    }
    out[b * 512 + j] = sm_;
    out[2048 + b * 512 + j] = sv;
}

// ---------------- host launcher ----------------
extern "C" void kernel_launch(void* const* d_in, const int* in_sizes, int n_in,
                              void* d_out, int out_size) {
    const float* x    = (const float*)d_in[0];
    const int*   mask = (const int*)d_in[1];
    const float* w1a = (const float*)d_in[2];
    const float* g1a = (const float*)d_in[3];
    const float* b1a = (const float*)d_in[4];
    const float* w1b = (const float*)d_in[5];
    const float* g1b = (const float*)d_in[6];
    const float* b1b = (const float*)d_in[7];
    const float* w2a = (const float*)d_in[8];
    const float* g2a = (const float*)d_in[9];
    const float* b2a = (const float*)d_in[10];
    const float* w2b = (const float*)d_in[11];
    const float* g2b = (const float*)d_in[12];
    const float* b2b = (const float*)d_in[13];
    const float* w3a = (const float*)d_in[14];
    const float* g3a = (const float*)d_in[15];
    const float* b3a = (const float*)d_in[16];
    const float* w3b = (const float*)d_in[17];
    const float* g3b = (const float*)d_in[18];
    const float* b3b = (const float*)d_in[19];
    const float* wm  = (const float*)d_in[20];
    const float* bm  = (const float*)d_in[21];
    const float* wv  = (const float*)d_in[22];
    const float* bv  = (const float*)d_in[23];

    float *bufA, *bufB, *m1, *m2, *m3, *part, *scale, *shift, *ppart, *cpart, *pooled;
    int* cnt;
    cudaGetSymbolAddress((void**)&bufA, g_bufA);
    cudaGetSymbolAddress((void**)&bufB, g_bufB);
    cudaGetSymbolAddress((void**)&m1, g_m1);
    cudaGetSymbolAddress((void**)&m2, g_m2);
    cudaGetSymbolAddress((void**)&m3, g_m3);
    cudaGetSymbolAddress((void**)&cnt, g_cnt);
    cudaGetSymbolAddress((void**)&part, g_part);
    cudaGetSymbolAddress((void**)&scale, g_scale);
    cudaGetSymbolAddress((void**)&shift, g_shift);
    cudaGetSymbolAddress((void**)&ppart, g_ppart);
    cudaGetSymbolAddress((void**)&cpart, g_cpart);
    cudaGetSymbolAddress((void**)&pooled, g_pooled);

    cudaMemsetAsync(cnt, 0, 3 * sizeof(int));

    // ---- block 1 ----
    pool_mask_kernel<int><<<4096, 256>>>(mask, m1, cnt + 0, 4, 64);
    conv1a_kernel<<<4096, 256>>>(x, mask, w1a, m1, bufA);
    bn_reduce<16><<<128, 256>>>(bufA, 1048576, part);
    bn_finalize<16><<<1, 16>>>(part, cnt + 0, g1a, b1a, scale, shift);
    bn_apply<16><<<(1048576 * 4 + 255) / 256, 256>>>(bufA, m1, scale, shift, 1048576);
    conv1b_kernel<<<2048, 256>>>(bufA, w1b, m1, bufB);
    bn_reduce<16><<<128, 256>>>(bufB, 1048576, part);
    bn_finalize<16><<<1, 16>>>(part, cnt + 0, g1b, b1b, scale, shift);
    bn_apply<16><<<(1048576 * 4 + 255) / 256, 256>>>(bufB, m1, scale, shift, 1048576);

    // ---- block 2 ----
    pool_mask_kernel<float><<<512, 256>>>(m1, m2, cnt + 1, 4, 32);
    conv_igemm<16, 64, 2><<<dim3(2048, 1), 256>>>(bufB, w2a, m2, bufA, 4, 64, 32);
    bn_reduce<64><<<128, 256>>>(bufA, 131072, part);
    bn_finalize<64><<<1, 64>>>(part, cnt + 1, g2a, b2a, scale, shift);
    bn_apply<64><<<(131072 * 16 + 255) / 256, 256>>>(bufA, m2, scale, shift, 131072);
    conv_igemm<64, 64, 1><<<dim3(2048, 1), 256>>>(bufA, w2b, m2, bufB, 4, 32, 32);
    bn_reduce<64><<<128, 256>>>(bufB, 131072, part);
    bn_finalize<64><<<1, 64>>>(part, cnt + 1, g2b, b2b, scale, shift);
    bn_apply<64><<<(131072 * 16 + 255) / 256, 256>>>(bufB, m2, scale, shift, 131072);

    // ---- block 3 ----
    pool_mask_kernel<float><<<64, 256>>>(m2, m3, cnt + 2, 4, 16);
    conv_igemm<64, 512, 2><<<dim3(256, 8), 256>>>(bufB, w3a, m3, bufA, 4, 32, 16);
    bn_reduce<512><<<128, 256>>>(bufA, 16384, part);
    bn_finalize<512><<<1, 512>>>(part, cnt + 2, g3a, b3a, scale, shift);
    bn_apply<512><<<(16384 * 128 + 255) / 256, 256>>>(bufA, m3, scale, shift, 16384);
    conv_igemm<512, 512, 1><<<dim3(256, 8), 256>>>(bufA, w3b, m3, bufB, 4, 16, 16);
    bn_reduce<512><<<128, 256>>>(bufB, 16384, part);
    bn_finalize<512><<<1, 512>>>(part, cnt + 2, g3b, b3b, scale, shift);
    bn_apply<512><<<(16384 * 128 + 255) / 256, 256>>>(bufB, m3, scale, shift, 16384);

    // ---- global pooling + heads ----
    pool_partial<<<dim3(4, 16), 512>>>(bufB, m3, ppart, cpart);
    pool_final<<<4, 512>>>(ppart, cpart, pooled);
    heads_kernel<<<4, 512>>>(pooled, wm, bm, wv, bv, (float*)d_out);

    (void)in_sizes; (void)n_in; (void)out_size;
}

// round 3
// speedup vs baseline: 1.0821x; 1.0821x over previous
#include <cuda_runtime.h>
#include <math.h>

typedef unsigned long long ull;

// ---------------- packed f32x2 helpers (Blackwell FFMA2) ----------------
__device__ __forceinline__ ull pack2(float lo, float hi) {
    ull r; asm("mov.b64 %0, {%1, %2};" : "=l"(r) : "f"(lo), "f"(hi)); return r;
}
__device__ __forceinline__ float2 unpack2(ull v) {
    float2 f; asm("mov.b64 {%0, %1}, %2;" : "=f"(f.x), "=f"(f.y) : "l"(v)); return f;
}
__device__ __forceinline__ void ffma2(ull& d, ull a, ull b) {
    asm("fma.rn.f32x2 %0, %1, %2, %3;" : "=l"(d) : "l"(a), "l"(b), "l"(d));
}

// ---------------- static scratch (no allocations allowed) ----------------
__device__ float g_bufA[16777216];   // 64 MB ping
__device__ float g_bufB[16777216];   // 64 MB pong
__device__ float g_m1[1048576];      // 4*64^3
__device__ float g_m2[131072];       // 4*32^3
__device__ float g_m3[16384];        // 4*16^3
__device__ int   g_cnt[3];
__device__ float g_part[128 * 1024]; // per-block BN partials (sum | sumsq)
__device__ float g_scale[512];
__device__ float g_shift[512];
__device__ float g_ppart[4 * 16 * 512];
__device__ float g_cpart[4 * 16];
__device__ float g_pooled[4 * 512];

#define EPSBN 1e-5f

// ---------------- mask pooling (2x2x2 max) + active count ----------------
template <typename T>
__global__ void pool_mask_kernel(const T* __restrict__ min_, float* __restrict__ mout,
                                 int* __restrict__ cnt, int B, int Dout) {
    int Din = Dout * 2;
    int M = B * Dout * Dout * Dout;
    int site = blockIdx.x * blockDim.x + threadIdx.x;
    int active = 0;
    if (site < M) {
        int ow = site % Dout; int t = site / Dout;
        int oh = t % Dout; t /= Dout;
        int od = t % Dout; int b = t / Dout;
        int iz0 = od * 2, iy0 = oh * 2, ix0 = ow * 2;
        bool a = false;
        #pragma unroll
        for (int dz = 0; dz < 2; dz++)
            #pragma unroll
            for (int dy = 0; dy < 2; dy++)
                #pragma unroll
                for (int dx = 0; dx < 2; dx++) {
                    T v = min_[(((long)(b * Din + iz0 + dz) * Din + iy0 + dy) * Din) + ix0 + dx];
                    a = a || (v != (T)0);
                }
        mout[site] = a ? 1.f : 0.f;
        active = a ? 1 : 0;
    }
    unsigned bal = __ballot_sync(0xffffffffu, active);
    __shared__ int ws[8];
    if ((threadIdx.x & 31) == 0) ws[threadIdx.x >> 5] = __popc(bal);
    __syncthreads();
    if (threadIdx.x == 0) {
        int t = 0;
        for (int i = 0; i < (int)(blockDim.x >> 5); i++) t += ws[i];
        atomicAdd(cnt, t);
    }
}

// ---------------- conv1a: 128^3 x1 -> 64^3 x16, stride 2 ----------------
__global__ void __launch_bounds__(256) conv1a_kernel(
    const float* __restrict__ x, const int* __restrict__ mask,
    const float* __restrict__ w, const float* __restrict__ m1, float* __restrict__ y) {
    __shared__ float wsh[432];
    for (int i = threadIdx.x; i < 432; i += 256) wsh[i] = w[i];
    __syncthreads();
    int site = blockIdx.x * 256 + threadIdx.x;
    int ow = site & 63; int t = site >> 6;
    int oh = t & 63; t >>= 6;
    int od = t & 63; int b = t >> 6;
    float acc[16];
    #pragma unroll
    for (int c = 0; c < 16; c++) acc[c] = 0.f;
    #pragma unroll
    for (int tz = 0; tz < 3; tz++) {
        int iz = od * 2 - 1 + tz;
        if ((unsigned)iz >= 128u) continue;
        #pragma unroll
        for (int ty = 0; ty < 3; ty++) {
            int iy = oh * 2 - 1 + ty;
            if ((unsigned)iy >= 128u) continue;
            #pragma unroll
            for (int tx = 0; tx < 3; tx++) {
                int ix = ow * 2 - 1 + tx;
                if ((unsigned)ix >= 128u) continue;
                int idx = ((b * 128 + iz) * 128 + iy) * 128 + ix;
                if (mask[idx]) {
                    float v = x[idx];
                    int tap = (tz * 3 + ty) * 3 + tx;
                    #pragma unroll
                    for (int c = 0; c < 16; c++) acc[c] += v * wsh[tap * 16 + c];
                }
            }
        }
    }
    float mk = m1[site];
    float* o = y + (long)site * 16;
    #pragma unroll
    for (int q = 0; q < 4; q++) {
        float4 v = make_float4(acc[q*4]*mk, acc[q*4+1]*mk, acc[q*4+2]*mk, acc[q*4+3]*mk);
        *(float4*)(o + q * 4) = v;
    }
}

// ---------------- conv1b: 64^3 16->16, stride 1, 2 sites/thread, f32x2 ----------------
__global__ void __launch_bounds__(256) conv1b_kernel(
    const float* __restrict__ in, const float* __restrict__ w,
    const float* __restrict__ m, float* __restrict__ out) {
    __shared__ __align__(16) float wsh[6912];
    for (int i = threadIdx.x; i < 6912; i += 256) wsh[i] = w[i];
    __syncthreads();
    int pair = blockIdx.x * 256 + threadIdx.x;  // 524288 pairs
    int s0 = pair * 2;
    int ow = s0 & 63; int t = s0 >> 6;
    int oh = t & 63; t >>= 6;
    int od = t & 63; int b = t >> 6;
    ull acc0p[8], acc1p[8];
    #pragma unroll
    for (int h = 0; h < 8; h++) { acc0p[h] = 0ull; acc1p[h] = 0ull; }
    #pragma unroll
    for (int tz = 0; tz < 3; tz++) {
        int iz = od - 1 + tz;
        if ((unsigned)iz >= 64u) continue;
        #pragma unroll
        for (int ty = 0; ty < 3; ty++) {
            int iy = oh - 1 + ty;
            if ((unsigned)iy >= 64u) continue;
            int rowbase = ((b * 64 + iz) * 64 + iy) * 64;
            #pragma unroll
            for (int tx = 0; tx < 3; tx++) {
                int ix0 = ow - 1 + tx;
                int ix1 = ix0 + 1;
                int tap = (tz * 3 + ty) * 3 + tx;
                const float* wp = wsh + tap * 256;
                bool ok0 = (unsigned)ix0 < 64u;
                bool ok1 = (unsigned)ix1 < 64u;
                float4 v0q[4], v1q[4];
                #pragma unroll
                for (int q = 0; q < 4; q++) {
                    v0q[q] = ok0 ? *(const float4*)(in + (long)(rowbase + ix0) * 16 + q * 4)
                                 : make_float4(0, 0, 0, 0);
                    v1q[q] = ok1 ? *(const float4*)(in + (long)(rowbase + ix1) * 16 + q * 4)
                                 : make_float4(0, 0, 0, 0);
                }
                const float* v0 = (const float*)v0q;
                const float* v1 = (const float*)v1q;
                #pragma unroll
                for (int ci = 0; ci < 16; ci++) {
                    ull a0d = pack2(v0[ci], v0[ci]);
                    ull a1d = pack2(v1[ci], v1[ci]);
                    const ull* wrow = (const ull*)(wp + ci * 16);
                    #pragma unroll
                    for (int h = 0; h < 8; h++) {
                        ull wv = wrow[h];
                        ffma2(acc0p[h], a0d, wv);
                        ffma2(acc1p[h], a1d, wv);
                    }
                }
            }
        }
    }
    float mk0 = m[s0], mk1 = m[s0 + 1];
    #pragma unroll
    for (int q = 0; q < 4; q++) {
        float2 e0 = unpack2(acc0p[2*q]), e1 = unpack2(acc0p[2*q+1]);
        *(float4*)(out + (long)s0 * 16 + q * 4) =
            make_float4(e0.x*mk0, e0.y*mk0, e1.x*mk0, e1.y*mk0);
        float2 f0 = unpack2(acc1p[2*q]), f1 = unpack2(acc1p[2*q+1]);
        *(float4*)(out + (long)(s0 + 1) * 16 + q * 4) =
            make_float4(f0.x*mk1, f0.y*mk1, f1.x*mk1, f1.y*mk1);
    }
}

// ---------------- implicit GEMM conv: BM=128, BK=16, f32x2, double-buffered ----------------
// Requires: CIN % 16 == 0 or CIN == 16; BK=16 chunk never straddles a tap.
template <int CIN, int COUT, int S, int BN>
__global__ void __launch_bounds__(256) conv_igemm2(
    const float* __restrict__ in, const float* __restrict__ w,
    const float* __restrict__ mout, float* __restrict__ out,
    int Din, int Dout) {
    constexpr int BM = 128;
    constexpr int BK = 16;
    constexpr int TN = BN / 16;            // 8 (BN=128) or 4 (BN=64)
    constexpr int KTOT = 27 * CIN;
    __shared__ __align__(16) float As[BK][BM];
    __shared__ __align__(16) float Bs[BK][BN];
    __shared__ int sB[BM], sZ[BM], sY[BM], sX[BM];

    const int tid = threadIdx.x;
    const int m0 = blockIdx.x * BM;
    const int n0 = blockIdx.y * BN;

    if (tid < BM) {
        int mm = m0 + tid;
        int ow = mm % Dout; int t = mm / Dout;
        int oh = t % Dout; t /= Dout;
        int od = t % Dout; int b = t / Dout;
        sB[tid] = b; sZ[tid] = od * S - 1; sY[tid] = oh * S - 1; sX[tid] = ow * S - 1;
    }
    __syncthreads();

    // A staging: thread handles site am, k-half ah (8 k's = 2 float4 along ci)
    const int am = tid & 127;
    const int ah = tid >> 7;
    const int aBb = sB[am], aZ = sZ[am], aY = sY[am], aX = sX[am];

    const int ty = tid >> 4, tx = tid & 15;

    ull acc[8][TN / 2];
    #pragma unroll
    for (int i = 0; i < 8; i++)
        #pragma unroll
        for (int j = 0; j < TN / 2; j++) acc[i][j] = 0ull;

    float4 aR0, aR1, bR0, bR1;

    auto loadA = [&](int k0) {
        int tap = k0 / CIN;
        int ci0 = k0 - tap * CIN + (ah << 3);
        int tz = tap / 9; int tr = tap - tz * 9;
        int tyy = tr / 3; int txx = tr - tyy * 3;
        int iz = aZ + tz, iy = aY + tyy, ix = aX + txx;
        aR0 = make_float4(0, 0, 0, 0);
        aR1 = aR0;
        if ((unsigned)iz < (unsigned)Din && (unsigned)iy < (unsigned)Din &&
            (unsigned)ix < (unsigned)Din) {
            int idx = (((aBb * Din + iz) * Din + iy) * Din + ix) * CIN + ci0;
            aR0 = *(const float4*)(in + idx);
            aR1 = *(const float4*)(in + idx + 4);
        }
    };
    auto storeA = [&]() {
        int kb = ah << 3;
        As[kb + 0][am] = aR0.x; As[kb + 1][am] = aR0.y;
        As[kb + 2][am] = aR0.z; As[kb + 3][am] = aR0.w;
        As[kb + 4][am] = aR1.x; As[kb + 5][am] = aR1.y;
        As[kb + 6][am] = aR1.z; As[kb + 7][am] = aR1.w;
    };
    auto loadB = [&](int k0) {
        if (BN == 128) {
            int kr = tid >> 5, n4 = (tid & 31) << 2;
            bR0 = *(const float4*)(w + (long)(k0 + kr) * COUT + n0 + n4);
            bR1 = *(const float4*)(w + (long)(k0 + kr + 8) * COUT + n0 + n4);
        } else {
            int kr = tid >> 4, n4 = (tid & 15) << 2;
            bR0 = *(const float4*)(w + (long)(k0 + kr) * COUT + n0 + n4);
        }
    };
    auto storeB = [&]() {
        if (BN == 128) {
            int kr = tid >> 5, n4 = (tid & 31) << 2;
            *(float4*)&Bs[kr][n4] = bR0;
            *(float4*)&Bs[kr + 8][n4] = bR1;
        } else {
            int kr = tid >> 4, n4 = (tid & 15) << 2;
            *(float4*)&Bs[kr][n4] = bR0;
        }
    };

    loadA(0); loadB(0);
    storeA(); storeB();
    __syncthreads();

    for (int k0 = 0; k0 < KTOT; k0 += BK) {
        bool more = (k0 + BK) < KTOT;
        if (more) { loadA(k0 + BK); loadB(k0 + BK); }
        #pragma unroll
        for (int kk = 0; kk < BK; kk++) {
            float4 a0 = *(const float4*)&As[kk][ty << 3];
            float4 a1 = *(const float4*)&As[kk][(ty << 3) + 4];
            ull ad[8];
            ad[0] = pack2(a0.x, a0.x); ad[1] = pack2(a0.y, a0.y);
            ad[2] = pack2(a0.z, a0.z); ad[3] = pack2(a0.w, a0.w);
            ad[4] = pack2(a1.x, a1.x); ad[5] = pack2(a1.y, a1.y);
            ad[6] = pack2(a1.z, a1.z); ad[7] = pack2(a1.w, a1.w);
            ull bd[TN / 2];
            #pragma unroll
            for (int j = 0; j < TN / 2; j++)
                bd[j] = *(const ull*)&Bs[kk][tx * TN + (j << 1)];
            #pragma unroll
            for (int i = 0; i < 8; i++)
                #pragma unroll
                for (int j = 0; j < TN / 2; j++)
                    ffma2(acc[i][j], ad[i], bd[j]);
        }
        __syncthreads();
        if (more) { storeA(); storeB(); __syncthreads(); }
    }

    #pragma unroll
    for (int i = 0; i < 8; i++) {
        int mm = m0 + (ty << 3) + i;
        float mk = mout[mm];
        #pragma unroll
        for (int q = 0; q < TN / 4; q++) {
            float2 e0 = unpack2(acc[i][2 * q]);
            float2 e1 = unpack2(acc[i][2 * q + 1]);
            *(float4*)(out + (long)mm * COUT + n0 + tx * TN + 4 * q) =
                make_float4(e0.x * mk, e0.y * mk, e1.x * mk, e1.y * mk);
        }
    }
}

// ---------------- BN: deterministic two-level reduction ----------------
template <int C>
__global__ void __launch_bounds__(256) bn_reduce(const float* __restrict__ y, int nsites,
                                                 float* __restrict__ part) {
    constexpr int GP = C / 4;       // threads per site
    constexpr int NG = 256 / GP;    // sites per block step
    int tid = threadIdx.x;
    int g = tid / GP;
    int lane = tid - g * GP;
    int c0 = lane * 4;
    float s0 = 0, s1 = 0, s2 = 0, s3 = 0;
    float q0 = 0, q1 = 0, q2 = 0, q3 = 0;
    for (int site = blockIdx.x * NG + g; site < nsites; site += gridDim.x * NG) {
        float4 v = *(const float4*)(y + (long)site * C + c0);
        s0 += v.x; s1 += v.y; s2 += v.z; s3 += v.w;
        q0 += v.x * v.x; q1 += v.y * v.y; q2 += v.z * v.z; q3 += v.w * v.w;
    }
    __shared__ float sm[NG][C];
    __shared__ float sq[NG][C];
    sm[g][c0 + 0] = s0; sm[g][c0 + 1] = s1; sm[g][c0 + 2] = s2; sm[g][c0 + 3] = s3;
    sq[g][c0 + 0] = q0; sq[g][c0 + 1] = q1; sq[g][c0 + 2] = q2; sq[g][c0 + 3] = q3;
    __syncthreads();
    for (int c = tid; c < C; c += 256) {
        float a = 0, b = 0;
        #pragma unroll 4
        for (int gg = 0; gg < NG; gg++) { a += sm[gg][c]; b += sq[gg][c]; }
        part[blockIdx.x * (2 * C) + c] = a;
        part[blockIdx.x * (2 * C) + C + c] = b;
    }
}

template <int C>
__global__ void __launch_bounds__(512) bn_finalize(
        const float* __restrict__ part, const int* __restrict__ cntp,
        const float* __restrict__ gamma, const float* __restrict__ beta,
        float* __restrict__ scale, float* __restrict__ shift) {
    constexpr int R = 512 / C;      // 32 / 8 / 1
    int c = threadIdx.x % C;
    int r = threadIdx.x / C;
    float s = 0, q = 0;
    for (int nb = r; nb < 128; nb += R) {
        s += part[nb * 2 * C + c];
        q += part[nb * 2 * C + C + c];
    }
    __shared__ float ss[512], qq[512];
    ss[threadIdx.x] = s; qq[threadIdx.x] = q;
    __syncthreads();
    if (r == 0) {
        for (int rr = 1; rr < R; rr++) { s += ss[rr * C + c]; q += qq[rr * C + c]; }
        float cnt = (float)cntp[0];
        float mean = s / cnt;
        float var = q / cnt - mean * mean;
        float sc = gamma[c] * rsqrtf(var + EPSBN);
        scale[c] = sc;
        shift[c] = beta[c] - mean * sc;
    }
}

template <int C>
__global__ void bn_apply(float* __restrict__ y, const float* __restrict__ m,
                         const float* __restrict__ scale, const float* __restrict__ shift,
                         int nsites) {
    __shared__ float sc[C], sh[C];
    for (int i = threadIdx.x; i < C; i += blockDim.x) { sc[i] = scale[i]; sh[i] = shift[i]; }
    __syncthreads();
    long total = (long)nsites * (C / 4);
    long i = (long)blockIdx.x * blockDim.x + threadIdx.x;
    if (i >= total) return;
    float4 v = ((float4*)y)[i];
    int cq = (int)(i % (C / 4)) * 4;
    float mk = m[i / (C / 4)];
    float a;
    a = v.x * sc[cq + 0] + sh[cq + 0]; v.x = (a > 0.f ? a : expm1f(a)) * mk;
    a = v.y * sc[cq + 1] + sh[cq + 1]; v.y = (a > 0.f ? a : expm1f(a)) * mk;
    a = v.z * sc[cq + 2] + sh[cq + 2]; v.z = (a > 0.f ? a : expm1f(a)) * mk;
    a = v.w * sc[cq + 3] + sh[cq + 3]; v.w = (a > 0.f ? a : expm1f(a)) * mk;
    ((float4*)y)[i] = v;
}

// ---------------- global pooling ----------------
__global__ void pool_partial(const float* __restrict__ y, const float* __restrict__ m3,
                             float* __restrict__ ppart, float* __restrict__ cpart) {
    int b = blockIdx.x;
    int g = blockIdx.y;
    int c = threadIdx.x; // 512
    float s = 0;
    int sbase = g * 256;
    for (int k = 0; k < 256; k++) s += y[((long)(b * 4096 + sbase + k)) * 512 + c];
    ppart[(b * 16 + g) * 512 + c] = s;
    __shared__ float red[512];
    red[c] = (c < 256) ? m3[b * 4096 + sbase + c] : 0.f;
    __syncthreads();
    for (int st = 256; st > 0; st >>= 1) {
        if (c < st) red[c] += red[c + st];
        __syncthreads();
    }
    if (c == 0) cpart[b * 16 + g] = red[0];
}

__global__ void pool_final(const float* __restrict__ ppart, const float* __restrict__ cpart,
                           float* __restrict__ pooled) {
    int b = blockIdx.x;
    int c = threadIdx.x;
    float s = 0, cnt = 0;
    for (int g = 0; g < 16; g++) {
        s += ppart[(b * 16 + g) * 512 + c];
        cnt += cpart[b * 16 + g];
    }
    pooled[b * 512 + c] = s / cnt;
}

// ---------------- heads ----------------
__global__ void heads_kernel(const float* __restrict__ pooled,
                             const float* __restrict__ wm, const float* __restrict__ bm,
                             const float* __restrict__ wv, const float* __restrict__ bv,
                             float* __restrict__ out) {
    int b = blockIdx.x;
    int j = threadIdx.x; // 512
    __shared__ float p[512];
    p[j] = pooled[b * 512 + j];
    __syncthreads();
    float sm_ = bm[j], sv = bv[j];
    for (int c = 0; c < 512; c++) {
        float pv = p[c];
        sm_ += pv * wm[c * 512 + j];
        sv += pv * wv[c * 512 + j];
    }
    out[b * 512 + j] = sm_;
    out[2048 + b * 512 + j] = sv;
}

// ---------------- host launcher ----------------
extern "C" void kernel_launch(void* const* d_in, const int* in_sizes, int n_in,
                              void* d_out, int out_size) {
    const float* x    = (const float*)d_in[0];
    const int*   mask = (const int*)d_in[1];
    const float* w1a = (const float*)d_in[2];
    const float* g1a = (const float*)d_in[3];
    const float* b1a = (const float*)d_in[4];
    const float* w1b = (const float*)d_in[5];
    const float* g1b = (const float*)d_in[6];
    const float* b1b = (const float*)d_in[7];
    const float* w2a = (const float*)d_in[8];
    const float* g2a = (const float*)d_in[9];
    const float* b2a = (const float*)d_in[10];
    const float* w2b = (const float*)d_in[11];
    const float* g2b = (const float*)d_in[12];
    const float* b2b = (const float*)d_in[13];
    const float* w3a = (const float*)d_in[14];
    const float* g3a = (const float*)d_in[15];
    const float* b3a = (const float*)d_in[16];
    const float* w3b = (const float*)d_in[17];
    const float* g3b = (const float*)d_in[18];
    const float* b3b = (const float*)d_in[19];
    const float* wm  = (const float*)d_in[20];
    const float* bm  = (const float*)d_in[21];
    const float* wv  = (const float*)d_in[22];
    const float* bv  = (const float*)d_in[23];

    float *bufA, *bufB, *m1, *m2, *m3, *part, *scale, *shift, *ppart, *cpart, *pooled;
    int* cnt;
    cudaGetSymbolAddress((void**)&bufA, g_bufA);
    cudaGetSymbolAddress((void**)&bufB, g_bufB);
    cudaGetSymbolAddress((void**)&m1, g_m1);
    cudaGetSymbolAddress((void**)&m2, g_m2);
    cudaGetSymbolAddress((void**)&m3, g_m3);
    cudaGetSymbolAddress((void**)&cnt, g_cnt);
    cudaGetSymbolAddress((void**)&part, g_part);
    cudaGetSymbolAddress((void**)&scale, g_scale);
    cudaGetSymbolAddress((void**)&shift, g_shift);
    cudaGetSymbolAddress((void**)&ppart, g_ppart);
    cudaGetSymbolAddress((void**)&cpart, g_cpart);
    cudaGetSymbolAddress((void**)&pooled, g_pooled);

    cudaMemsetAsync(cnt, 0, 3 * sizeof(int));

    // ---- block 1 ----
    pool_mask_kernel<int><<<4096, 256>>>(mask, m1, cnt + 0, 4, 64);
    conv1a_kernel<<<4096, 256>>>(x, mask, w1a, m1, bufA);
    bn_reduce<16><<<128, 256>>>(bufA, 1048576, part);
    bn_finalize<16><<<1, 512>>>(part, cnt + 0, g1a, b1a, scale, shift);
    bn_apply<16><<<(1048576 * 4 + 255) / 256, 256>>>(bufA, m1, scale, shift, 1048576);
    conv1b_kernel<<<2048, 256>>>(bufA, w1b, m1, bufB);
    bn_reduce<16><<<128, 256>>>(bufB, 1048576, part);
    bn_finalize<16><<<1, 512>>>(part, cnt + 0, g1b, b1b, scale, shift);
    bn_apply<16><<<(1048576 * 4 + 255) / 256, 256>>>(bufB, m1, scale, shift, 1048576);

    // ---- block 2 ----
    pool_mask_kernel<float><<<512, 256>>>(m1, m2, cnt + 1, 4, 32);
    conv_igemm2<16, 64, 2, 64><<<dim3(1024, 1), 256>>>(bufB, w2a, m2, bufA, 64, 32);
    bn_reduce<64><<<128, 256>>>(bufA, 131072, part);
    bn_finalize<64><<<1, 512>>>(part, cnt + 1, g2a, b2a, scale, shift);
    bn_apply<64><<<(131072 * 16 + 255) / 256, 256>>>(bufA, m2, scale, shift, 131072);
    conv_igemm2<64, 64, 1, 64><<<dim3(1024, 1), 256>>>(bufA, w2b, m2, bufB, 32, 32);
    bn_reduce<64><<<128, 256>>>(bufB, 131072, part);
    bn_finalize<64><<<1, 512>>>(part, cnt + 1, g2b, b2b, scale, shift);
    bn_apply<64><<<(131072 * 16 + 255) / 256, 256>>>(bufB, m2, scale, shift, 131072);

    // ---- block 3 ----
    pool_mask_kernel<float><<<64, 256>>>(m2, m3, cnt + 2, 4, 16);
    conv_igemm2<64, 512, 2, 128><<<dim3(128, 4), 256>>>(bufB, w3a, m3, bufA, 32, 16);
    bn_reduce<512><<<128, 256>>>(bufA, 16384, part);
    bn_finalize<512><<<1, 512>>>(part, cnt + 2, g3a, b3a, scale, shift);
    bn_apply<512><<<(16384 * 128 + 255) / 256, 256>>>(bufA, m3, scale, shift, 16384);
    conv_igemm2<512, 512, 1, 128><<<dim3(128, 4), 256>>>(bufA, w3b, m3, bufB, 16, 16);
    bn_reduce<512><<<128, 256>>>(bufB, 16384, part);
    bn_finalize<512><<<1, 512>>>(part, cnt + 2, g3b, b3b, scale, shift);
    bn_apply<512><<<(16384 * 128 + 255) / 256, 256>>>(bufB, m3, scale, shift, 16384);

    // ---- global pooling + heads ----
    pool_partial<<<dim3(4, 16), 512>>>(bufB, m3, ppart, cpart);
    pool_final<<<4, 512>>>(ppart, cpart, pooled);
    heads_kernel<<<4, 512>>>(pooled, wm, bm, wv, bv, (float*)d_out);

    (void)in_sizes; (void)n_in; (void)out_size;
}